// round 16
// baseline (speedup 1.0000x reference)
#include <cuda_runtime.h>
#include <cuda_fp16.h>
#include <cstdint>
#include <math.h>

#define TILE_E   128
#define NTHREADS 512
#define HDIM     128
#define ASTH     144u  // half-tile row stride (36 words -> conflict-free ldsm)
#define WST      272u  // weight-tile row stride (68 words -> conflict-free ldsm)

// ---------------- global scratch: transposed fp16 weights ----------------
__device__ __half g_W1T[128 * 512];   // [n][k] from W1[k][n]
__device__ __half g_W2T[64 * 128];    // [n][k] from W2[k][n]

__global__ void prep_kernel(const float* __restrict__ W1, const float* __restrict__ W2) {
    int i = blockIdx.x * blockDim.x + threadIdx.x;
    if (i < 128 * 512) {
        int n = i >> 9, k = i & 511;
        g_W1T[i] = __float2half_rn(W1[k * 128 + n]);
    }
    if (i < 64 * 128) {
        int n = i >> 7, k = i & 127;
        g_W2T[i] = __float2half_rn(W2[k * 64 + n]);
    }
}

// ---------------- helpers ----------------
__device__ __forceinline__ uint32_t smem_u32(const void* p) {
    uint32_t a;
    asm("{ .reg .u64 t; cvta.to.shared.u64 t, %1; cvt.u32.u64 %0, t; }" : "=r"(a) : "l"(p));
    return a;
}
#define STS32(addr, v) \
    asm volatile("st.shared.b32 [%0], %1;" :: "r"(addr), "r"(v) : "memory")
#define CP16(saddr, gaddr) \
    asm volatile("cp.async.cg.shared.global [%0], [%1], 16;" \
        :: "r"(saddr), "l"(gaddr) : "memory")
#define CP_COMMIT() asm volatile("cp.async.commit_group;" ::: "memory")
#define CP_WAIT0()  asm volatile("cp.async.wait_group 0;" ::: "memory")
#define LDSM4(r, a) \
    asm volatile("ldmatrix.sync.aligned.m8n8.x4.shared.b16 {%0,%1,%2,%3}, [%4];" \
        : "=r"((r)[0]), "=r"((r)[1]), "=r"((r)[2]), "=r"((r)[3]) : "r"(a))
#define MMAF16(c, a, b0v, b1v) \
    asm volatile("mma.sync.aligned.m16n8k16.row.col.f32.f16.f16.f32 " \
        "{%0,%1,%2,%3}, {%4,%5,%6,%7}, {%8,%9}, {%0,%1,%2,%3};" \
        : "+f"((c)[0]), "+f"((c)[1]), "+f"((c)[2]), "+f"((c)[3]) \
        : "r"((a)[0]), "r"((a)[1]), "r"((a)[2]), "r"((a)[3]), "r"(b0v), "r"(b1v))

__device__ __forceinline__ uint32_t packh2(float x0, float x1) {
    uint32_t r;
    asm("cvt.rn.f16x2.f32 %0, %1, %2;" : "=r"(r) : "f"(x1), "f"(x0));
    return r;
}

// dynamic smem: W1 segs (4 x 128x272) | W2 (64x272) | per-group S,D half-tiles
#define W1S(i)  (sb + (uint32_t)(i) * 34816u)
#define W2_OFF  139264u
#define AG_OFF  156672u          // + g*36864 ; S at +0, D at +18432
#define SMEM_DYN 230400

__global__ __launch_bounds__(NTHREADS, 1)
void link_mma_kernel(const float* __restrict__ z,
                     const void* __restrict__ ei_raw,
                     const float* __restrict__ b1g,
                     const float* __restrict__ b2g,
                     const float* __restrict__ w3g,
                     const float* __restrict__ b3g,
                     float* __restrict__ out,
                     int E, int nNodes)
{
    extern __shared__ char dynraw[];
    __shared__ int s_is64;

    const int tid = threadIdx.x;
    const int wid = tid >> 5;
    const int lid = tid & 31;
    const uint32_t sb = smem_u32(dynraw);

    if (tid == 0) {
        const long long* e64 = (const long long*)ei_raw;
        int ok = 1;
        #pragma unroll
        for (int i = 0; i < 8; ++i) {
            long long v = e64[i];
            if (v < 0 || v >= (long long)nNodes) { ok = 0; break; }
        }
        s_is64 = ok;
    }

    // weights -> smem (once, whole CTA)
    {
        const char* srcW1 = (const char*)g_W1T;
        #pragma unroll
        for (int it = 0; it < 16; ++it) {
            int idx = tid + it * NTHREADS;     // 0..8191
            int seg = idx >> 11;
            int n   = (idx >> 4) & 127;
            int q   = idx & 15;
            uint32_t goff = (uint32_t)n * 1024u + (uint32_t)seg * 256u + (uint32_t)q * 16u;
            CP16(W1S(seg) + (uint32_t)n * WST + (uint32_t)q * 16u, srcW1 + goff);
        }
        const char* srcW2 = (const char*)g_W2T;
        #pragma unroll
        for (int it = 0; it < 2; ++it) {
            int idx = tid + it * NTHREADS;     // 0..1023
            int n = idx >> 4, q = idx & 15;
            CP16(sb + W2_OFF + (uint32_t)n * WST + (uint32_t)q * 16u,
                 srcW2 + (uint32_t)n * 256u + (uint32_t)q * 16u);
        }
        CP_COMMIT();
        CP_WAIT0();
    }
    __syncthreads();

    const int is64 = s_is64;
    const uint32_t lrow = (uint32_t)(lid & 15);
    const uint32_t lcol = (uint32_t)(lid >> 4) * 8;

    const int g     = wid >> 3;        // 0/1 : independent tile pipeline
    const int wg    = wid & 7;
    const int tid_g = tid & 255;
    const int pair  = wg >> 1;         // 0..3 : 32-row edge band
    const int side  = wg & 1;          // 0: src/S + cols 0-63, 1: dst/D + cols 64-127
    const uint32_t Sb = sb + AG_OFF + (uint32_t)g * 36864u;
    const uint32_t Db = Sb + 18432u;
    const uint32_t Ab = side ? Db : Sb;   // the buffer this warp fills

    #define GBAR() asm volatile("bar.sync %0, 256;" :: "r"(g + 1) : "memory")
    #define PBAR() asm volatile("bar.sync %0, 64;"  :: "r"(3 + g * 4 + pair) : "memory")

    const int nTiles = (E + TILE_E - 1) / TILE_E;

    for (int t = blockIdx.x * 2 + g; t < nTiles; t += gridDim.x * 2) {
        const int e0 = t * TILE_E;

        GBAR();   // prev tile's cross-pair partial reads done before refill

        // lane l holds the edge index for row pair*32 + l (src for side0, dst side1)
        int myidx;
        {
            int e = e0 + pair * 32 + lid;
            if (e >= E) e = 0;
            size_t off = side ? ((size_t)E + e) : (size_t)e;
            myidx = is64 ? (int)((const long long*)ei_raw)[off]
                         : ((const int*)ei_raw)[off];
            myidx = min(max(myidx, 0), nNodes - 1);
        }

        float acc[2][8][4];
        #pragma unroll
        for (int a = 0; a < 2; ++a)
            #pragma unroll
            for (int b = 0; b < 8; ++b)
                #pragma unroll
                for (int d = 0; d < 4; ++d) acc[a][b][d] = 0.f;

        #pragma unroll
        for (int h = 0; h < 2; ++h) {
            // ---- fill own 32-row band: side0 -> S (src), side1 -> D (dst) ----
            #pragma unroll
            for (int i = 0; i < 32; ++i) {
                int ridx = __shfl_sync(0xffffffffu, myidx, i);
                float2 v = *(const float2*)(z + (size_t)ridx * HDIM + h * 64 + 2 * lid);
                STS32(Ab + (uint32_t)(pair * 32 + i) * ASTH + (uint32_t)lid * 4u,
                      packh2(v.x, v.y));
            }
            PBAR();

            // ---- MMA: frags once, prod/diff in registers, 4 segments ----
            {
                const uint32_t sT = Sb + (pair * 32u + lrow) * ASTH + lcol * 2u;
                const uint32_t dT = Db + (pair * 32u + lrow) * ASTH + lcol * 2u;
                #pragma unroll
                for (int ks = 0; ks < 4; ++ks) {
                    const uint32_t ko = (uint32_t)ks * 32u;
                    uint32_t sf[2][4], df[2][4], pf[2][4], qf[2][4];
                    LDSM4(sf[0], sT + ko);
                    LDSM4(sf[1], sT + ko + 16u * ASTH);
                    LDSM4(df[0], dT + ko);
                    LDSM4(df[1], dT + ko + 16u * ASTH);
                    #pragma unroll
                    for (int a2 = 0; a2 < 2; ++a2)
                        #pragma unroll
                        for (int j = 0; j < 4; ++j) {
                            __half2 sh = *reinterpret_cast<__half2*>(&sf[a2][j]);
                            __half2 dh = *reinterpret_cast<__half2*>(&df[a2][j]);
                            __half2 ph = __hmul2(sh, dh);
                            __half2 qh = __habs2(__hsub2(sh, dh));
                            pf[a2][j] = *reinterpret_cast<uint32_t*>(&ph);
                            qf[a2][j] = *reinterpret_cast<uint32_t*>(&qh);
                        }
                    #pragma unroll
                    for (int seg = 0; seg < 4; ++seg) {
                        const uint32_t (*af)[4] =
                            (seg == 0) ? sf : (seg == 1) ? df : (seg == 2) ? pf : qf;
                        const uint32_t bT = W1S(seg) + (side * 64u + lrow) * WST
                                          + (uint32_t)h * 128u + lcol * 2u + ko;
                        #pragma unroll
                        for (int gg = 0; gg < 2; ++gg) {
                            uint32_t b[2][4];
                            LDSM4(b[0], bT + (uint32_t)(gg * 2 + 0) * 16u * WST);
                            LDSM4(b[1], bT + (uint32_t)(gg * 2 + 1) * 16u * WST);
                            #pragma unroll
                            for (int fm = 0; fm < 2; ++fm)
                                #pragma unroll
                                for (int q = 0; q < 4; ++q) {
                                    const int gi = q >> 1, sel = q & 1;
                                    const int fn = gg * 4 + q;
                                    MMAF16(acc[fm][fn], af[fm], b[gi][sel], b[gi][sel + 2]);
                                }
                        }
                    }
                }
            }
            PBAR();   // pair's frag loads done before next-half fill overwrites
        }

        // ---- epilogue 1: relu(+b1) -> fp16 -> h1 (k 0-63 -> S, k 64-127 -> D) ----
        {
            const uint32_t reg = side ? Db : Sb;
            #pragma unroll
            for (int fm = 0; fm < 2; ++fm)
                #pragma unroll
                for (int fn = 0; fn < 8; ++fn) {
                    const int lc   = fn * 8 + (lid & 3) * 2;
                    const int col  = side * 64 + lc;
                    const int row0 = pair * 32 + fm * 16 + (lid >> 2);
                    const float bb0 = __ldg(&b1g[col]);
                    const float bb1 = __ldg(&b1g[col + 1]);
                    float x0 = fmaxf(acc[fm][fn][0] + bb0, 0.f);
                    float x1 = fmaxf(acc[fm][fn][1] + bb1, 0.f);
                    float x2 = fmaxf(acc[fm][fn][2] + bb0, 0.f);
                    float x3 = fmaxf(acc[fm][fn][3] + bb1, 0.f);
                    uint32_t o0 = (uint32_t)row0 * ASTH + (uint32_t)lc * 2u;
                    STS32(reg + o0, packh2(x0, x1));
                    STS32(reg + o0 + 8u * ASTH, packh2(x2, x3));
                }
        }
        PBAR();   // pair band's h1 complete (GEMM2 reads only own band)

        // ---- GEMM2: h1 [128,128] x W2^T [64,128]; warp: 32 rows x 32 cols ----
        float acc2[2][4][4];
        #pragma unroll
        for (int a = 0; a < 2; ++a)
            #pragma unroll
            for (int b = 0; b < 4; ++b)
                #pragma unroll
                for (int d = 0; d < 4; ++d) acc2[a][b][d] = 0.f;
        #pragma unroll
        for (int h = 0; h < 2; ++h) {
            const uint32_t a2T = (h ? Db : Sb) + (pair * 32u + lrow) * ASTH + lcol * 2u;
            const uint32_t b2T = sb + W2_OFF + (side * 32u + lrow) * WST
                               + (uint32_t)h * 128u + lcol * 2u;
            #pragma unroll
            for (int ks = 0; ks < 4; ++ks) {
                const uint32_t ko = (uint32_t)ks * 32u;
                uint32_t a[2][4], b[2][4];
                LDSM4(a[0], a2T + ko);
                LDSM4(a[1], a2T + ko + 16u * ASTH);
                LDSM4(b[0], b2T + ko);
                LDSM4(b[1], b2T + ko + 16u * WST);
                #pragma unroll
                for (int fm = 0; fm < 2; ++fm)
                    #pragma unroll
                    for (int fn = 0; fn < 4; ++fn) {
                        const int gi = fn >> 1, sel = fn & 1;
                        MMAF16(acc2[fm][fn], a[fm], b[gi][sel], b[gi][sel + 2]);
                    }
            }
        }
        GBAR();   // ALL pairs' GEMM2 reads done before partials overwrite S rows 0-7

        // ---- epilogue 2: relu(+b2), dot w3, quad-reduce, partials -> S ----
        #pragma unroll
        for (int fm = 0; fm < 2; ++fm)
            #pragma unroll
            for (int rh = 0; rh < 2; ++rh) {
                float s = 0.f;
                #pragma unroll
                for (int fn = 0; fn < 4; ++fn) {
                    const int col = side * 32 + fn * 8 + (lid & 3) * 2;
                    float h0 = fmaxf(acc2[fm][fn][rh * 2 + 0] + __ldg(&b2g[col]),     0.f);
                    float h1 = fmaxf(acc2[fm][fn][rh * 2 + 1] + __ldg(&b2g[col + 1]), 0.f);
                    s = fmaf(h0, __ldg(&w3g[col]), fmaf(h1, __ldg(&w3g[col + 1]), s));
                }
                s += __shfl_xor_sync(0xffffffffu, s, 1);
                s += __shfl_xor_sync(0xffffffffu, s, 2);
                if ((lid & 3) == 0) {
                    int row = pair * 32 + fm * 16 + rh * 8 + (lid >> 2);
                    STS32(Sb + (uint32_t)(row * 2 + side) * 4u, __float_as_uint(s));
                }
            }
        GBAR();   // final sum crosses pairs
        if (tid_g < TILE_E) {
            const float* part = (const float*)(dynraw + AG_OFF + g * 36864);
            int e = e0 + tid_g;
            if (e < E)
                out[e] = part[tid_g * 2 + 0] + part[tid_g * 2 + 1] + __ldg(&b3g[0]);
        }
    }
    #undef GBAR
    #undef PBAR
}

extern "C" void kernel_launch(void* const* d_in, const int* in_sizes, int n_in,
                              void* d_out, int out_size) {
    const float* z  = (const float*)d_in[0];
    const void*  ei = d_in[1];
    const float* W1 = (const float*)d_in[2];
    const float* b1 = (const float*)d_in[3];
    const float* W2 = (const float*)d_in[4];
    const float* b2 = (const float*)d_in[5];
    const float* W3 = (const float*)d_in[6];
    const float* b3 = (const float*)d_in[7];
    float* out = (float*)d_out;

    const int E      = out_size;
    const int nNodes = in_sizes[0] / HDIM;

    prep_kernel<<<256, 256>>>(W1, W2);

    cudaFuncSetAttribute(link_mma_kernel,
                         cudaFuncAttributeMaxDynamicSharedMemorySize, SMEM_DYN);

    int dev = 0, smCount = 148;
    cudaGetDevice(&dev);
    cudaDeviceGetAttribute(&smCount, cudaDevAttrMultiProcessorCount, dev);
    const int nTiles = (E + TILE_E - 1) / TILE_E;
    int grid = (nTiles + 1) / 2;
    if (grid > smCount) grid = smCount;

    link_mma_kernel<<<grid, NTHREADS, SMEM_DYN>>>(z, ei, b1, b2, W3, b3,
                                                  out, E, nNodes);
}

// round 17
// speedup vs baseline: 1.0656x; 1.0656x over previous
#include <cuda_runtime.h>
#include <cuda_fp16.h>
#include <cstdint>
#include <math.h>

#define TILE_E   128
#define NTHREADS 512
#define HDIM     128
#define ASTH     144u  // half-tile row stride (36 words -> conflict-free ldsm)
#define WST      272u  // weight-tile row stride (68 words -> conflict-free ldsm)

// ---------------- global scratch: transposed fp16 weights ----------------
__device__ __half g_W1T[128 * 512];   // [n][k] from W1[k][n]
__device__ __half g_W2T[64 * 128];    // [n][k] from W2[k][n]

__global__ void prep_kernel(const float* __restrict__ W1, const float* __restrict__ W2) {
    int i = blockIdx.x * blockDim.x + threadIdx.x;
    if (i < 128 * 512) {
        int n = i >> 9, k = i & 511;
        g_W1T[i] = __float2half_rn(W1[k * 128 + n]);
    }
    if (i < 64 * 128) {
        int n = i >> 7, k = i & 127;
        g_W2T[i] = __float2half_rn(W2[k * 64 + n]);
    }
}

// ---------------- helpers ----------------
__device__ __forceinline__ uint32_t smem_u32(const void* p) {
    uint32_t a;
    asm("{ .reg .u64 t; cvta.to.shared.u64 t, %1; cvt.u32.u64 %0, t; }" : "=r"(a) : "l"(p));
    return a;
}
#define STS32(addr, v) \
    asm volatile("st.shared.b32 [%0], %1;" :: "r"(addr), "r"(v) : "memory")
#define STS64(addr, v0, v1) \
    asm volatile("st.shared.v2.b32 [%0], {%1,%2};" :: "r"(addr), "r"(v0), "r"(v1) : "memory")
#define LDS64(v0, v1, addr) \
    asm volatile("ld.shared.v2.b32 {%0,%1}, [%2];" : "=r"(v0), "=r"(v1) : "r"(addr))
#define CP16(saddr, gaddr) \
    asm volatile("cp.async.cg.shared.global [%0], [%1], 16;" \
        :: "r"(saddr), "l"(gaddr) : "memory")
#define CP_COMMIT() asm volatile("cp.async.commit_group;" ::: "memory")
#define CP_WAIT0()  asm volatile("cp.async.wait_group 0;" ::: "memory")
#define LDSM4(r, a) \
    asm volatile("ldmatrix.sync.aligned.m8n8.x4.shared.b16 {%0,%1,%2,%3}, [%4];" \
        : "=r"((r)[0]), "=r"((r)[1]), "=r"((r)[2]), "=r"((r)[3]) : "r"(a))
#define MMAF16(c, a, b0v, b1v) \
    asm volatile("mma.sync.aligned.m16n8k16.row.col.f32.f16.f16.f32 " \
        "{%0,%1,%2,%3}, {%4,%5,%6,%7}, {%8,%9}, {%0,%1,%2,%3};" \
        : "+f"((c)[0]), "+f"((c)[1]), "+f"((c)[2]), "+f"((c)[3]) \
        : "r"((a)[0]), "r"((a)[1]), "r"((a)[2]), "r"((a)[3]), "r"(b0v), "r"(b1v))

__device__ __forceinline__ uint32_t packh2(float x0, float x1) {
    uint32_t r;
    asm("cvt.rn.f16x2.f32 %0, %1, %2;" : "=r"(r) : "f"(x1), "f"(x0));
    return r;
}

// dynamic smem: W1 segs (4 x 128x272) | W2 (64x272) | per-group S,D half-tiles
#define W1S(i)  (sb + (uint32_t)(i) * 34816u)
#define W2_OFF  139264u
#define AG_OFF  156672u          // + g*36864 ; S at +0, D at +18432
#define SMEM_DYN 230400

__global__ __launch_bounds__(NTHREADS, 1)
void link_mma_kernel(const float* __restrict__ z,
                     const void* __restrict__ ei_raw,
                     const float* __restrict__ b1g,
                     const float* __restrict__ b2g,
                     const float* __restrict__ w3g,
                     const float* __restrict__ b3g,
                     float* __restrict__ out,
                     int E, int nNodes)
{
    extern __shared__ char dynraw[];
    __shared__ int s_is64;

    const int tid = threadIdx.x;
    const int wid = tid >> 5;
    const int lid = tid & 31;
    const uint32_t sb = smem_u32(dynraw);

    if (tid == 0) {
        const long long* e64 = (const long long*)ei_raw;
        int ok = 1;
        #pragma unroll
        for (int i = 0; i < 8; ++i) {
            long long v = e64[i];
            if (v < 0 || v >= (long long)nNodes) { ok = 0; break; }
        }
        s_is64 = ok;
    }

    // weights -> smem (once, whole CTA)
    {
        const char* srcW1 = (const char*)g_W1T;
        #pragma unroll
        for (int it = 0; it < 16; ++it) {
            int idx = tid + it * NTHREADS;     // 0..8191
            int seg = idx >> 11;
            int n   = (idx >> 4) & 127;
            int q   = idx & 15;
            uint32_t goff = (uint32_t)n * 1024u + (uint32_t)seg * 256u + (uint32_t)q * 16u;
            CP16(W1S(seg) + (uint32_t)n * WST + (uint32_t)q * 16u, srcW1 + goff);
        }
        const char* srcW2 = (const char*)g_W2T;
        #pragma unroll
        for (int it = 0; it < 2; ++it) {
            int idx = tid + it * NTHREADS;     // 0..1023
            int n = idx >> 4, q = idx & 15;
            CP16(sb + W2_OFF + (uint32_t)n * WST + (uint32_t)q * 16u,
                 srcW2 + (uint32_t)n * 256u + (uint32_t)q * 16u);
        }
        CP_COMMIT();
        CP_WAIT0();
    }
    __syncthreads();

    const int is64 = s_is64;
    const uint32_t lrow = (uint32_t)(lid & 15);
    const uint32_t lcol = (uint32_t)(lid >> 4) * 8;

    const int g     = wid >> 3;        // 0/1 : independent tile pipeline
    const int wg    = wid & 7;
    const int tid_g = tid & 255;
    const uint32_t Sb = sb + AG_OFF + (uint32_t)g * 36864u;
    const uint32_t Db = Sb + 18432u;

    #define GBAR() asm volatile("bar.sync %0, 256;" :: "r"(g + 1) : "memory")

    const int wmG = wg >> 1;           // GEMM1: 32 rows x 64 cols
    const int wnG = wg & 1;
    const int wm2 = wg >> 1;           // GEMM2: 32 rows x 32 cols
    const int wn2 = wg & 1;

    const int nTiles = (E + TILE_E - 1) / TILE_E;

    for (int t = blockIdx.x * 2 + g; t < nTiles; t += gridDim.x * 2) {
        const int e0 = t * TILE_E;

        GBAR();   // prev tile fully done (incl. partial reads from S)

        // per-warp edge indices in registers: lanes 0-15 src, 16-31 dst
        int myidx;
        {
            int e = e0 + wg * 16 + (lid & 15);
            if (e >= E) e = 0;
            if (lid < 16)
                myidx = is64 ? (int)((const long long*)ei_raw)[e] : ((const int*)ei_raw)[e];
            else
                myidx = is64 ? (int)((const long long*)ei_raw)[(size_t)E + e]
                             : ((const int*)ei_raw)[(size_t)E + e];
            myidx = min(max(myidx, 0), nNodes - 1);
        }

        float acc[2][8][4];
        #pragma unroll
        for (int a = 0; a < 2; ++a)
            #pragma unroll
            for (int b = 0; b < 8; ++b)
                #pragma unroll
                for (int d = 0; d < 4; ++d) acc[a][b][d] = 0.f;

        auto mma_half = [&](uint32_t Abuf, int seg, int h) {
            const uint32_t aT = Abuf + (wmG * 32u + lrow) * ASTH + lcol * 2u;
            const uint32_t bT = W1S(seg) + (wnG * 64u + lrow) * WST
                              + (uint32_t)h * 128u + lcol * 2u;
            #pragma unroll
            for (int ks = 0; ks < 4; ++ks) {
                const uint32_t ko = (uint32_t)ks * 32u;
                uint32_t a[2][4];
                LDSM4(a[0], aT + ko);
                LDSM4(a[1], aT + ko + 16u * ASTH);
                #pragma unroll
                for (int gg = 0; gg < 2; ++gg) {
                    uint32_t b[2][4];
                    #pragma unroll
                    for (int gi = 0; gi < 2; ++gi) {
                        uint32_t rb = ko + (uint32_t)(gg * 2 + gi) * 16u * WST;
                        LDSM4(b[gi], bT + rb);
                    }
                    #pragma unroll
                    for (int fm = 0; fm < 2; ++fm)
                        #pragma unroll
                        for (int q = 0; q < 4; ++q) {
                            const int gi = q >> 1, sel = q & 1;
                            const int fn = gg * 4 + q;
                            MMAF16(acc[fm][fn], a[fm], b[gi][sel], b[gi][sel + 2]);
                        }
                }
            }
        };

        #pragma unroll
        for (int h = 0; h < 2; ++h) {
            // ---- fill S (src half) and D (dst half) from global ----
            #pragma unroll
            for (int i = 0; i < 16; ++i) {
                int si = __shfl_sync(0xffffffffu, myidx, i);
                int di = __shfl_sync(0xffffffffu, myidx, 16 + i);
                float2 vsv = *(const float2*)(z + (size_t)si * HDIM + h * 64 + 2 * lid);
                float2 vdv = *(const float2*)(z + (size_t)di * HDIM + h * 64 + 2 * lid);
                uint32_t off = (uint32_t)(wg * 16 + i) * ASTH + (uint32_t)lid * 4u;
                STS32(Sb + off, packh2(vsv.x, vsv.y));
                STS32(Db + off, packh2(vdv.x, vdv.y));
            }
            GBAR();
            mma_half(Sb, 0, h);
            mma_half(Db, 1, h);
            GBAR();
            // ---- in-place: S -> prod, D -> |diff| (v2 64-bit smem ops) ----
            #pragma unroll
            for (int i = 0; i < 8; ++i) {
                uint32_t off = (uint32_t)(wg * 16 + (lid >> 4) * 8 + i) * ASTH
                             + (uint32_t)(lid & 15) * 8u;
                uint32_t su0, su1, du0, du1;
                LDS64(su0, su1, Sb + off);
                LDS64(du0, du1, Db + off);
                __half2 s0 = *reinterpret_cast<__half2*>(&su0);
                __half2 s1 = *reinterpret_cast<__half2*>(&su1);
                __half2 d0 = *reinterpret_cast<__half2*>(&du0);
                __half2 d1 = *reinterpret_cast<__half2*>(&du1);
                __half2 p0 = __hmul2(s0, d0), p1 = __hmul2(s1, d1);
                __half2 q0 = __habs2(__hsub2(s0, d0)), q1 = __habs2(__hsub2(s1, d1));
                STS64(Sb + off, *reinterpret_cast<uint32_t*>(&p0),
                                *reinterpret_cast<uint32_t*>(&p1));
                STS64(Db + off, *reinterpret_cast<uint32_t*>(&q0),
                                *reinterpret_cast<uint32_t*>(&q1));
            }
            GBAR();
            mma_half(Sb, 2, h);
            mma_half(Db, 3, h);
            GBAR();
        }

        // ---- epilogue 1: relu(+b1) -> fp16 -> h1 halves (cols<64 -> S, else D) ----
        {
            const uint32_t reg = (wnG == 0) ? Sb : Db;
            float bb0[8], bb1[8];
            #pragma unroll
            for (int fn = 0; fn < 8; ++fn) {
                const int col = wnG * 64 + fn * 8 + (lid & 3) * 2;
                bb0[fn] = __ldg(&b1g[col]);
                bb1[fn] = __ldg(&b1g[col + 1]);
            }
            #pragma unroll
            for (int fm = 0; fm < 2; ++fm)
                #pragma unroll
                for (int fn = 0; fn < 8; ++fn) {
                    const int lc   = fn * 8 + (lid & 3) * 2;
                    const int row0 = wmG * 32 + fm * 16 + (lid >> 2);
                    float x0 = fmaxf(acc[fm][fn][0] + bb0[fn], 0.f);
                    float x1 = fmaxf(acc[fm][fn][1] + bb1[fn], 0.f);
                    float x2 = fmaxf(acc[fm][fn][2] + bb0[fn], 0.f);
                    float x3 = fmaxf(acc[fm][fn][3] + bb1[fn], 0.f);
                    uint32_t o0 = (uint32_t)row0 * ASTH + (uint32_t)lc * 2u;
                    STS32(reg + o0, packh2(x0, x1));
                    STS32(reg + o0 + 8u * ASTH, packh2(x2, x3));
                }
        }
        GBAR();

        // ---- GEMM2: h1 [128,128] x W2^T [64,128], warp tile 32x32, k halves ----
        float acc2[2][4][4];
        #pragma unroll
        for (int a = 0; a < 2; ++a)
            #pragma unroll
            for (int b = 0; b < 4; ++b)
                #pragma unroll
                for (int d = 0; d < 4; ++d) acc2[a][b][d] = 0.f;
        #pragma unroll
        for (int h = 0; h < 2; ++h) {
            const uint32_t a2T = (h ? Db : Sb) + (wm2 * 32u + lrow) * ASTH + lcol * 2u;
            const uint32_t b2T = sb + W2_OFF + (wn2 * 32u + lrow) * WST
                               + (uint32_t)h * 128u + lcol * 2u;
            #pragma unroll
            for (int ks = 0; ks < 4; ++ks) {
                const uint32_t ko = (uint32_t)ks * 32u;
                uint32_t a[2][4], b[2][4];
                LDSM4(a[0], a2T + ko);
                LDSM4(a[1], a2T + ko + 16u * ASTH);
                LDSM4(b[0], b2T + ko);
                LDSM4(b[1], b2T + ko + 16u * WST);
                #pragma unroll
                for (int fm = 0; fm < 2; ++fm)
                    #pragma unroll
                    for (int fn = 0; fn < 4; ++fn) {
                        const int gi = fn >> 1, sel = fn & 1;
                        MMAF16(acc2[fm][fn], a[fm], b[gi][sel], b[gi][sel + 2]);
                    }
            }
        }
        GBAR();   // all GEMM2 reads of S/D done before partials overwrite

        // ---- epilogue 2: relu(+b2), dot w3, quad-reduce, partials -> S ----
        {
            float b2r[4], b2r1[4], w3r[4], w3r1[4];
            #pragma unroll
            for (int fn = 0; fn < 4; ++fn) {
                const int col = wn2 * 32 + fn * 8 + (lid & 3) * 2;
                b2r[fn]  = __ldg(&b2g[col]);
                b2r1[fn] = __ldg(&b2g[col + 1]);
                w3r[fn]  = __ldg(&w3g[col]);
                w3r1[fn] = __ldg(&w3g[col + 1]);
            }
            #pragma unroll
            for (int fm = 0; fm < 2; ++fm)
                #pragma unroll
                for (int rh = 0; rh < 2; ++rh) {
                    float s = 0.f;
                    #pragma unroll
                    for (int fn = 0; fn < 4; ++fn) {
                        float h0 = fmaxf(acc2[fm][fn][rh * 2 + 0] + b2r[fn],  0.f);
                        float h1 = fmaxf(acc2[fm][fn][rh * 2 + 1] + b2r1[fn], 0.f);
                        s = fmaf(h0, w3r[fn], fmaf(h1, w3r1[fn], s));
                    }
                    s += __shfl_xor_sync(0xffffffffu, s, 1);
                    s += __shfl_xor_sync(0xffffffffu, s, 2);
                    if ((lid & 3) == 0) {
                        int row = wm2 * 32 + fm * 16 + rh * 8 + (lid >> 2);
                        STS32(Sb + (uint32_t)(row * 2 + wn2) * 4u, __float_as_uint(s));
                    }
                }
        }
        GBAR();
        if (tid_g < TILE_E) {
            const float* part = (const float*)(dynraw + AG_OFF + g * 36864);
            int e = e0 + tid_g;
            if (e < E)
                out[e] = part[tid_g * 2 + 0] + part[tid_g * 2 + 1] + __ldg(&b3g[0]);
        }
    }
    #undef GBAR
}

extern "C" void kernel_launch(void* const* d_in, const int* in_sizes, int n_in,
                              void* d_out, int out_size) {
    const float* z  = (const float*)d_in[0];
    const void*  ei = d_in[1];
    const float* W1 = (const float*)d_in[2];
    const float* b1 = (const float*)d_in[3];
    const float* W2 = (const float*)d_in[4];
    const float* b2 = (const float*)d_in[5];
    const float* W3 = (const float*)d_in[6];
    const float* b3 = (const float*)d_in[7];
    float* out = (float*)d_out;

    const int E      = out_size;
    const int nNodes = in_sizes[0] / HDIM;

    prep_kernel<<<256, 256>>>(W1, W2);

    cudaFuncSetAttribute(link_mma_kernel,
                         cudaFuncAttributeMaxDynamicSharedMemorySize, SMEM_DYN);

    int dev = 0, smCount = 148;
    cudaGetDevice(&dev);
    cudaDeviceGetAttribute(&smCount, cudaDevAttrMultiProcessorCount, dev);
    const int nTiles = (E + TILE_E - 1) / TILE_E;
    int grid = (nTiles + 1) / 2;
    if (grid > smCount) grid = smCount;

    link_mma_kernel<<<grid, NTHREADS, SMEM_DYN>>>(z, ei, b1, b2, W3, b3,
                                                  out, E, nNodes);
}